// round 1
// baseline (speedup 1.0000x reference)
#include <cuda_runtime.h>
#include <math.h>

#define BATCH 16
#define SEQ   4096
#define DIM   1280
#define TOK   77
#define CDIM  768
#define HEADS 8
#define DHEAD 160
#define JDIM  616   /* HEADS*TOK */

// Scratch (static device globals: allocation-free per harness rules)
__device__ float g_K [BATCH*TOK*DIM];                 // [b*77+t][1280]
__device__ float g_V [BATCH*TOK*DIM];                 // [b*77+t][1280]
__device__ float g_A [BATCH*DIM*JDIM];                // [b][c][j]   j=h*77+t
__device__ float g_B2[BATCH*JDIM*DIM];                // [b][j][e2]
__device__ float g_S [(size_t)BATCH*SEQ*JDIM];        // [b][s][j] scores -> probs

// ---------------------------------------------------------------------------
// Generic fp32 tiled GEMM, C[M,N] = A[M,K] @ B, 128x128x8 tiles, 256 threads,
// 8x8 per-thread microtile. Two B layouts:
//   gemm_nn: B is [K,N] row-major
//   gemm_nt: B is [N,K] row-major (i.e. C = A @ B^T)
// Batched via blockIdx.z with element strides. Optional bias added over N.
// Requires K % 8 == 0, N % 4 == 0, K % 4 == 0 (holds: 768/1280/616).
// ---------------------------------------------------------------------------

__global__ __launch_bounds__(256) void gemm_nn(
    const float* __restrict__ A, const float* __restrict__ B,
    float* __restrict__ C, const float* __restrict__ bias,
    int M, int N, int K, long sA, long sB, long sC)
{
    A += (long)blockIdx.z * sA;
    B += (long)blockIdx.z * sB;
    C += (long)blockIdx.z * sC;
    const int m0 = blockIdx.y * 128;
    const int n0 = blockIdx.x * 128;

    __shared__ float As[8][128];
    __shared__ float Bs[8][128];

    const int tid  = threadIdx.x;
    const int arow = tid >> 1;            // 0..127
    const int acol = (tid & 1) * 4;       // 0 or 4
    const int brow = tid >> 5;            // 0..7
    const int bcol = (tid & 31) * 4;      // 0..124
    const int tr   = (tid >> 4) * 8;      // 0..120
    const int tc   = (tid & 15) * 8;      // 0..120

    float acc[8][8];
    #pragma unroll
    for (int i = 0; i < 8; i++)
        #pragma unroll
        for (int j = 0; j < 8; j++) acc[i][j] = 0.f;

    for (int k0 = 0; k0 < K; k0 += 8) {
        // load A tile (transposed into smem)
        {
            const int gm = m0 + arow;
            float4 v = make_float4(0.f, 0.f, 0.f, 0.f);
            if (gm < M) v = *reinterpret_cast<const float4*>(A + (long)gm * K + k0 + acol);
            As[acol + 0][arow] = v.x; As[acol + 1][arow] = v.y;
            As[acol + 2][arow] = v.z; As[acol + 3][arow] = v.w;
        }
        // load B tile
        {
            const int gk = k0 + brow;
            const int gn = n0 + bcol;
            float4 v = make_float4(0.f, 0.f, 0.f, 0.f);
            if (gn + 4 <= N) {
                v = *reinterpret_cast<const float4*>(B + (long)gk * N + gn);
            } else {
                const float* p = B + (long)gk * N;
                if (gn + 0 < N) v.x = p[gn + 0];
                if (gn + 1 < N) v.y = p[gn + 1];
                if (gn + 2 < N) v.z = p[gn + 2];
            }
            *reinterpret_cast<float4*>(&Bs[brow][bcol]) = v;
        }
        __syncthreads();
        #pragma unroll
        for (int kk = 0; kk < 8; kk++) {
            float ar[8], br[8];
            #pragma unroll
            for (int i = 0; i < 8; i++) ar[i] = As[kk][tr + i];
            #pragma unroll
            for (int j = 0; j < 8; j++) br[j] = Bs[kk][tc + j];
            #pragma unroll
            for (int i = 0; i < 8; i++)
                #pragma unroll
                for (int j = 0; j < 8; j++)
                    acc[i][j] = fmaf(ar[i], br[j], acc[i][j]);
        }
        __syncthreads();
    }
    #pragma unroll
    for (int i = 0; i < 8; i++) {
        const int gm = m0 + tr + i;
        if (gm >= M) continue;
        #pragma unroll
        for (int j = 0; j < 8; j++) {
            const int gn = n0 + tc + j;
            if (gn < N)
                C[(long)gm * N + gn] = acc[i][j] + (bias ? bias[gn] : 0.f);
        }
    }
}

__global__ __launch_bounds__(256) void gemm_nt(
    const float* __restrict__ A, const float* __restrict__ Bt,
    float* __restrict__ C, const float* __restrict__ bias,
    int M, int N, int K, long sA, long sB, long sC)
{
    A  += (long)blockIdx.z * sA;
    Bt += (long)blockIdx.z * sB;
    C  += (long)blockIdx.z * sC;
    const int m0 = blockIdx.y * 128;
    const int n0 = blockIdx.x * 128;

    __shared__ float As[8][128];
    __shared__ float Bs[8][128];

    const int tid  = threadIdx.x;
    const int arow = tid >> 1;
    const int acol = (tid & 1) * 4;
    const int tr   = (tid >> 4) * 8;
    const int tc   = (tid & 15) * 8;

    float acc[8][8];
    #pragma unroll
    for (int i = 0; i < 8; i++)
        #pragma unroll
        for (int j = 0; j < 8; j++) acc[i][j] = 0.f;

    for (int k0 = 0; k0 < K; k0 += 8) {
        {
            const int gm = m0 + arow;
            float4 v = make_float4(0.f, 0.f, 0.f, 0.f);
            if (gm < M) v = *reinterpret_cast<const float4*>(A + (long)gm * K + k0 + acol);
            As[acol + 0][arow] = v.x; As[acol + 1][arow] = v.y;
            As[acol + 2][arow] = v.z; As[acol + 3][arow] = v.w;
        }
        {
            const int gn = n0 + arow;    // reuse mapping: 128 rows of B^T
            float4 v = make_float4(0.f, 0.f, 0.f, 0.f);
            if (gn < N) v = *reinterpret_cast<const float4*>(Bt + (long)gn * K + k0 + acol);
            Bs[acol + 0][arow] = v.x; Bs[acol + 1][arow] = v.y;
            Bs[acol + 2][arow] = v.z; Bs[acol + 3][arow] = v.w;
        }
        __syncthreads();
        #pragma unroll
        for (int kk = 0; kk < 8; kk++) {
            float ar[8], br[8];
            #pragma unroll
            for (int i = 0; i < 8; i++) ar[i] = As[kk][tr + i];
            #pragma unroll
            for (int j = 0; j < 8; j++) br[j] = Bs[kk][tc + j];
            #pragma unroll
            for (int i = 0; i < 8; i++)
                #pragma unroll
                for (int j = 0; j < 8; j++)
                    acc[i][j] = fmaf(ar[i], br[j], acc[i][j]);
        }
        __syncthreads();
    }
    #pragma unroll
    for (int i = 0; i < 8; i++) {
        const int gm = m0 + tr + i;
        if (gm >= M) continue;
        #pragma unroll
        for (int j = 0; j < 8; j++) {
            const int gn = n0 + tc + j;
            if (gn < N)
                C[(long)gm * N + gn] = acc[i][j] + (bias ? bias[gn] : 0.f);
        }
    }
}

// ---------------------------------------------------------------------------
// fold_A: A[b][c][h*77+t] = d^-0.5 * sum_e wq[h*160+e][c] * K[b*77+t][h*160+e]
// grid (10 c-tiles, 8 heads, 16 batches), 256 threads.
// ---------------------------------------------------------------------------
__global__ __launch_bounds__(256) void fold_A(
    const float* __restrict__ wq, const float* __restrict__ Kmat,
    float* __restrict__ Aout)
{
    const int b = blockIdx.z, h = blockIdx.y;
    const int c0 = blockIdx.x * 128;
    __shared__ float Ws[16][128];   // Ws[e][c]
    __shared__ float Ks[16][80];    // Ks[e][t], t padded to 80

    const int tid  = threadIdx.x;
    const int tcid = tid & 15;      // c group -> base tcid*8
    const int ttid = tid >> 4;      // t group -> base ttid*5
    const float scale = 0.07905694150420949f;  // 160^-0.5

    float acc[8][5];
    #pragma unroll
    for (int i = 0; i < 8; i++)
        #pragma unroll
        for (int j = 0; j < 5; j++) acc[i][j] = 0.f;

    for (int e0 = 0; e0 < DHEAD; e0 += 16) {
        {
            const int cc = (tid & 31) * 4;
            #pragma unroll
            for (int r = 0; r < 2; r++) {
                const int k = (tid >> 5) + r * 8;
                float4 v = *reinterpret_cast<const float4*>(
                    wq + (long)(h * DHEAD + e0 + k) * DIM + c0 + cc);
                *reinterpret_cast<float4*>(&Ws[k][cc]) = v;
            }
        }
        for (int idx = tid; idx < TOK * 16; idx += 256) {
            const int t = idx >> 4, k = idx & 15;
            Ks[k][t] = Kmat[(long)(b * TOK + t) * DIM + h * DHEAD + e0 + k];
        }
        for (int idx = tid; idx < 3 * 16; idx += 256) {
            Ks[idx & 15][TOK + (idx >> 4)] = 0.f;
        }
        __syncthreads();
        #pragma unroll
        for (int k = 0; k < 16; k++) {
            float w[8], kv[5];
            #pragma unroll
            for (int i = 0; i < 8; i++) w[i] = Ws[k][tcid * 8 + i];
            #pragma unroll
            for (int j = 0; j < 5; j++) kv[j] = Ks[k][ttid * 5 + j];
            #pragma unroll
            for (int i = 0; i < 8; i++)
                #pragma unroll
                for (int j = 0; j < 5; j++)
                    acc[i][j] = fmaf(w[i], kv[j], acc[i][j]);
        }
        __syncthreads();
    }
    #pragma unroll
    for (int i = 0; i < 8; i++) {
        const int c = c0 + tcid * 8 + i;
        #pragma unroll
        for (int j = 0; j < 5; j++) {
            const int t = ttid * 5 + j;
            if (t < TOK)
                Aout[((long)b * DIM + c) * JDIM + h * TOK + t] = acc[i][j] * scale;
        }
    }
}

// ---------------------------------------------------------------------------
// fold_B: B2[b][h*77+t][e2] = sum_e V[b*77+t][h*160+e] * wout[e2][h*160+e]
// grid (10 e2-tiles, 8 heads, 16 batches), 256 threads.
// ---------------------------------------------------------------------------
__global__ __launch_bounds__(256) void fold_B(
    const float* __restrict__ wout, const float* __restrict__ Vmat,
    float* __restrict__ B2)
{
    const int b = blockIdx.z, h = blockIdx.y;
    const int n0 = blockIdx.x * 128;
    __shared__ float Vs[16][80];    // Vs[e][t]
    __shared__ float Ws[16][128];   // Ws[e][n]

    const int tid  = threadIdx.x;
    const int tcid = tid & 15;      // n group -> base tcid*8
    const int ttid = tid >> 4;      // t group -> base ttid*5

    float acc[5][8];
    #pragma unroll
    for (int j = 0; j < 5; j++)
        #pragma unroll
        for (int i = 0; i < 8; i++) acc[j][i] = 0.f;

    for (int e0 = 0; e0 < DHEAD; e0 += 16) {
        for (int idx = tid; idx < 128 * 16; idx += 256) {
            const int n = idx >> 4, k = idx & 15;
            Ws[k][n] = wout[(long)(n0 + n) * DIM + h * DHEAD + e0 + k];
        }
        for (int idx = tid; idx < TOK * 16; idx += 256) {
            const int t = idx >> 4, k = idx & 15;
            Vs[k][t] = Vmat[(long)(b * TOK + t) * DIM + h * DHEAD + e0 + k];
        }
        for (int idx = tid; idx < 3 * 16; idx += 256) {
            Vs[idx & 15][TOK + (idx >> 4)] = 0.f;
        }
        __syncthreads();
        #pragma unroll
        for (int k = 0; k < 16; k++) {
            float vv[5], ww[8];
            #pragma unroll
            for (int j = 0; j < 5; j++) vv[j] = Vs[k][ttid * 5 + j];
            #pragma unroll
            for (int i = 0; i < 8; i++) ww[i] = Ws[k][tcid * 8 + i];
            #pragma unroll
            for (int j = 0; j < 5; j++)
                #pragma unroll
                for (int i = 0; i < 8; i++)
                    acc[j][i] = fmaf(vv[j], ww[i], acc[j][i]);
        }
        __syncthreads();
    }
    #pragma unroll
    for (int j = 0; j < 5; j++) {
        const int t = ttid * 5 + j;
        if (t >= TOK) continue;
        #pragma unroll
        for (int i = 0; i < 8; i++) {
            const int n = n0 + tcid * 8 + i;
            B2[((long)b * JDIM + h * TOK + t) * DIM + n] = acc[j][i];
        }
    }
}

// ---------------------------------------------------------------------------
// softmax over each 77-group of the scores. One warp per (b,s,h).
// ---------------------------------------------------------------------------
__global__ __launch_bounds__(256) void softmax77(float* __restrict__ Smat)
{
    const int gw   = blockIdx.x * 8 + (threadIdx.x >> 5);
    const int lane = threadIdx.x & 31;
    const long base = (long)(gw >> 3) * JDIM + (gw & 7) * TOK;

    const float NEG = -1e30f;
    float x0 = Smat[base + lane];
    float x1 = Smat[base + 32 + lane];
    float x2 = (lane < 13) ? Smat[base + 64 + lane] : NEG;

    float m = fmaxf(x0, fmaxf(x1, x2));
    #pragma unroll
    for (int o = 16; o > 0; o >>= 1)
        m = fmaxf(m, __shfl_xor_sync(0xffffffffu, m, o));

    float e0 = expf(x0 - m);
    float e1 = expf(x1 - m);
    float e2 = (lane < 13) ? expf(x2 - m) : 0.f;
    float s = e0 + e1 + e2;
    #pragma unroll
    for (int o = 16; o > 0; o >>= 1)
        s += __shfl_xor_sync(0xffffffffu, s, o);

    const float inv = 1.f / s;
    Smat[base + lane]      = e0 * inv;
    Smat[base + 32 + lane] = e1 * inv;
    if (lane < 13) Smat[base + 64 + lane] = e2 * inv;
}

// ---------------------------------------------------------------------------
extern "C" void kernel_launch(void* const* d_in, const int* in_sizes, int n_in,
                              void* d_out, int out_size)
{
    const float* X  = (const float*)d_in[0];   // [16,4096,1280]
    const float* E  = (const float*)d_in[1];   // [16,77,768]
    const float* wq = (const float*)d_in[2];   // [1280,1280]
    const float* wk = (const float*)d_in[3];   // [1280,768]
    const float* wv = (const float*)d_in[4];   // [1280,768]
    const float* wo = (const float*)d_in[5];   // [1280,1280]
    const float* bo = (const float*)d_in[6];   // [1280]
    float* out = (float*)d_out;                // [16,4096,1280]

    float *pK, *pV, *pA, *pB2, *pS;
    cudaGetSymbolAddress((void**)&pK,  g_K);
    cudaGetSymbolAddress((void**)&pV,  g_V);
    cudaGetSymbolAddress((void**)&pA,  g_A);
    cudaGetSymbolAddress((void**)&pB2, g_B2);
    cudaGetSymbolAddress((void**)&pS,  g_S);

    // K/V projections: [1232,768] @ [1280,768]^T -> [1232,1280]
    gemm_nt<<<dim3(10, 10, 1), 256>>>(E, wk, pK, nullptr,
                                      BATCH * TOK, DIM, CDIM, 0, 0, 0);
    gemm_nt<<<dim3(10, 10, 1), 256>>>(E, wv, pV, nullptr,
                                      BATCH * TOK, DIM, CDIM, 0, 0, 0);

    // folded matrices
    fold_A<<<dim3(10, 8, 16), 256>>>(wq, pK, pA);
    fold_B<<<dim3(10, 8, 16), 256>>>(wo, pV, pB2);

    // scores: per batch X[4096,1280] @ A[1280,616] -> S[4096,616]
    gemm_nn<<<dim3(5, 32, 16), 256>>>(X, pA, pS, nullptr,
                                      SEQ, JDIM, DIM,
                                      (long)SEQ * DIM, (long)DIM * JDIM,
                                      (long)SEQ * JDIM);

    // softmax over 77-groups
    softmax77<<<BATCH * SEQ * 8 / 8, 256>>>(pS);

    // output: per batch P[4096,616] @ B2[616,1280] + bias -> out[4096,1280]
    gemm_nn<<<dim3(10, 32, 16), 256>>>(pS, pB2, out, bo,
                                       SEQ, DIM, JDIM,
                                       (long)SEQ * JDIM, (long)JDIM * DIM,
                                       (long)SEQ * DIM);
}

// round 3
// speedup vs baseline: 2.2177x; 2.2177x over previous
#include <cuda_runtime.h>
#include <cuda_bf16.h>
#include <math.h>
#include <stdint.h>

#define BATCH 16
#define SEQ   4096
#define DIM   1280
#define TOK   77
#define CDIM  768
#define HEADS 8
#define DHEAD 160
#define JDIM  616
#define JPAD  640

// ---------------------------------------------------------------------------
// Scratch (static device globals)
// ---------------------------------------------------------------------------
__device__ __align__(256) float g_K [BATCH*TOK*DIM];
__device__ __align__(256) float g_V [BATCH*TOK*DIM];
__device__ __align__(256) float g_S [(size_t)BATCH*SEQ*JPAD];          // scores/probs fp32
__device__ __align__(256) __nv_bfloat16 g_Xh[(size_t)BATCH*SEQ*DIM];   // X split hi
__device__ __align__(256) __nv_bfloat16 g_Xl[(size_t)BATCH*SEQ*DIM];   // X split lo
__device__ __align__(256) __nv_bfloat16 g_Ah[(size_t)BATCH*JPAD*DIM];  // AfoldT [b][j][c] hi
__device__ __align__(256) __nv_bfloat16 g_Al[(size_t)BATCH*JPAD*DIM];
__device__ __align__(256) __nv_bfloat16 g_Bh[(size_t)BATCH*DIM*JPAD];  // B2T [b][e2][j] hi
__device__ __align__(256) __nv_bfloat16 g_Bl[(size_t)BATCH*DIM*JPAD];
__device__ __align__(256) __nv_bfloat16 g_Ph[(size_t)BATCH*SEQ*JPAD];  // probs split hi
__device__ __align__(256) __nv_bfloat16 g_Pl[(size_t)BATCH*SEQ*JPAD];

// ---------------------------------------------------------------------------
// helpers
// ---------------------------------------------------------------------------
__device__ __forceinline__ uint32_t smem_u32(const void* p) {
    uint32_t a;
    asm("{ .reg .u64 t; cvta.to.shared.u64 t, %1; cvt.u32.u64 %0, t; }"
        : "=r"(a) : "l"(p));
    return a;
}

#define SWZ128(o) ((o) ^ (((o) >> 3) & 0x70))

__device__ __forceinline__ void cp16(uint32_t s, const void* g) {
    asm volatile("cp.async.cg.shared.global [%0], [%1], 16;" :: "r"(s), "l"(g));
}
#define CP_COMMIT() asm volatile("cp.async.commit_group;" ::: "memory")

__device__ __forceinline__ void ldsm4(uint32_t& r0, uint32_t& r1,
                                      uint32_t& r2, uint32_t& r3, uint32_t addr) {
    asm volatile("ldmatrix.sync.aligned.m8n8.x4.shared.b16 {%0,%1,%2,%3}, [%4];"
                 : "=r"(r0), "=r"(r1), "=r"(r2), "=r"(r3) : "r"(addr));
}

__device__ __forceinline__ void mma16816(float* c, uint32_t a0, uint32_t a1,
                                         uint32_t a2, uint32_t a3,
                                         uint32_t b0, uint32_t b1) {
    asm volatile(
        "mma.sync.aligned.m16n8k16.row.col.f32.bf16.bf16.f32 "
        "{%0,%1,%2,%3}, {%4,%5,%6,%7}, {%8,%9}, {%0,%1,%2,%3};"
        : "+f"(c[0]), "+f"(c[1]), "+f"(c[2]), "+f"(c[3])
        : "r"(a0), "r"(a1), "r"(a2), "r"(a3), "r"(b0), "r"(b1));
}

// ---------------------------------------------------------------------------
// warp-MMA GEMM:  C[m][n] = sum_k A[m][k]*B[n][k]   (3-pass bf16 split, fp32)
// CTA tile 128x128, 8 warps (4M x 2N), warp tile 32x64.
// KC=64 per chunk; smem stage holds 4 tiles (Ah, Al, Bh, Bl) of 128x64 bf16.
// 2-stage cp.async double buffer.
// ---------------------------------------------------------------------------
#define KC 64
#define TILE_B 16384                     /* 128 rows x 128 bytes */
#define STAGE_B (4*TILE_B)               /* 64 KB */
#define MM_SMEM (2*STAGE_B)              /* 128 KB */

__global__ __launch_bounds__(256, 1)
void mma_gemm(const __nv_bfloat16* __restrict__ Ah, const __nv_bfloat16* __restrict__ Al,
              const __nv_bfloat16* __restrict__ Bh, const __nv_bfloat16* __restrict__ Bl,
              float* __restrict__ C, const float* __restrict__ bias,
              int K, int ldc, long sA, long sB, long sC)
{
    extern __shared__ __align__(1024) char smem[];
    const uint32_t sbase = smem_u32(smem);
    const int tid  = threadIdx.x;
    const int wid  = tid >> 5;
    const int lane = tid & 31;
    const int wm   = wid & 3;            // 0..3 : M slice of 32
    const int wn   = wid >> 2;           // 0..1 : N slice of 64

    const long rowA = (long)blockIdx.z * sA + (long)(blockIdx.y * 128) * K;
    const long rowB = (long)blockIdx.z * sB + (long)(blockIdx.x * 128) * K;

    // ---- per-thread cp.async slots: 4096 16B units across 4 tiles ----
    uint32_t soff[16];
    const char* gp[16];
    #pragma unroll
    for (int i = 0; i < 16; ++i) {
        int idx = tid + i * 256;
        int t = idx >> 10;               // 0:Ah 1:Al 2:Bh 3:Bl
        int r = (idx >> 3) & 127;
        int u = idx & 7;
        soff[i] = (uint32_t)(t * TILE_B) + SWZ128((uint32_t)(r * 128 + u * 16));
        const __nv_bfloat16* base =
            (t == 0) ? (Ah + rowA) : (t == 1) ? (Al + rowA)
          : (t == 2) ? (Bh + rowB) : (Bl + rowB);
        gp[i] = (const char*)(base + (long)r * K + u * 8);
    }

    // ---- ldmatrix address pre-computation ----
    // A fragment (m16k16): row = m0 + (lane&15), colByte = (lane>>4)*16 + kk*32
    uint32_t aRowOff[2], aXor[2];
    #pragma unroll
    for (int mi = 0; mi < 2; ++mi) {
        int r = wm * 32 + mi * 16 + (lane & 15);
        aRowOff[mi] = (uint32_t)(r * 128);
        aXor[mi]    = (uint32_t)((r & 7) * 16);
    }
    const uint32_t aG = (uint32_t)((lane >> 4) * 16);

    // B fragment pair (n16k16): row = n0 + (lane&7) + ((lane>>4)<<3),
    //                           colByte = ((lane>>3)&1)*16 + kk*32
    uint32_t bRowOff[4], bXor[4];
    #pragma unroll
    for (int q = 0; q < 4; ++q) {
        int r = wn * 64 + q * 16 + (lane & 7) + ((lane >> 4) << 3);
        bRowOff[q] = (uint32_t)(r * 128);
        bXor[q]    = (uint32_t)((r & 7) * 16);
    }
    const uint32_t bG = (uint32_t)(((lane >> 3) & 1) * 16);

    float acc[2][8][4];
    #pragma unroll
    for (int mi = 0; mi < 2; ++mi)
        #pragma unroll
        for (int ni = 0; ni < 8; ++ni)
            #pragma unroll
            for (int e = 0; e < 4; ++e) acc[mi][ni][e] = 0.f;

    const int nk = K / KC;

    // prologue: chunk 0 -> stage 0
    #pragma unroll
    for (int i = 0; i < 16; ++i) cp16(sbase + soff[i], gp[i]);
    CP_COMMIT();
    #pragma unroll
    for (int i = 0; i < 16; ++i) gp[i] += 128;

    for (int k = 0; k < nk; ++k) {
        if (k + 1 < nk) {
            const uint32_t sb = sbase + ((k + 1) & 1) * STAGE_B;
            #pragma unroll
            for (int i = 0; i < 16; ++i) cp16(sb + soff[i], gp[i]);
            CP_COMMIT();
            #pragma unroll
            for (int i = 0; i < 16; ++i) gp[i] += 128;
            asm volatile("cp.async.wait_group 1;" ::: "memory");
        } else {
            asm volatile("cp.async.wait_group 0;" ::: "memory");
        }
        __syncthreads();

        const uint32_t st = sbase + (k & 1) * STAGE_B;
        // 3 passes: (Ah,Bh), (Ah,Bl), (Al,Bh)
        #pragma unroll
        for (int pass = 0; pass < 3; ++pass) {
            const uint32_t aT = st + ((pass == 2) ? TILE_B : 0u);
            const uint32_t bT = st + 2 * TILE_B + ((pass == 1) ? TILE_B : 0u);
            #pragma unroll
            for (int kk = 0; kk < 4; ++kk) {
                const uint32_t kb = (uint32_t)(kk * 32);
                uint32_t a[2][4];
                #pragma unroll
                for (int mi = 0; mi < 2; ++mi)
                    ldsm4(a[mi][0], a[mi][1], a[mi][2], a[mi][3],
                          aT + aRowOff[mi] + ((aG + kb) ^ aXor[mi]));
                uint32_t b[4][4];
                #pragma unroll
                for (int q = 0; q < 4; ++q)
                    ldsm4(b[q][0], b[q][1], b[q][2], b[q][3],
                          bT + bRowOff[q] + ((bG + kb) ^ bXor[q]));
                #pragma unroll
                for (int mi = 0; mi < 2; ++mi)
                    #pragma unroll
                    for (int q = 0; q < 4; ++q) {
                        mma16816(acc[mi][q * 2 + 0],
                                 a[mi][0], a[mi][1], a[mi][2], a[mi][3],
                                 b[q][0], b[q][1]);
                        mma16816(acc[mi][q * 2 + 1],
                                 a[mi][0], a[mi][1], a[mi][2], a[mi][3],
                                 b[q][2], b[q][3]);
                    }
            }
        }
        __syncthreads();
    }

    // ---- epilogue ----
    const int row0 = blockIdx.y * 128 + wm * 32 + (lane >> 2);
    const int col0 = blockIdx.x * 128 + wn * 64 + (lane & 3) * 2;
    float* Cb = C + (long)blockIdx.z * sC;
    #pragma unroll
    for (int mi = 0; mi < 2; ++mi) {
        #pragma unroll
        for (int ni = 0; ni < 8; ++ni) {
            const int r = row0 + mi * 16;
            const int c = col0 + ni * 8;
            float bx = 0.f, by = 0.f;
            if (bias) { bx = bias[c]; by = bias[c + 1]; }
            float2 v0 = make_float2(acc[mi][ni][0] + bx, acc[mi][ni][1] + by);
            float2 v1 = make_float2(acc[mi][ni][2] + bx, acc[mi][ni][3] + by);
            *reinterpret_cast<float2*>(Cb + (long)r * ldc + c)       = v0;
            *reinterpret_cast<float2*>(Cb + (long)(r + 8) * ldc + c) = v1;
        }
    }
}

// ---------------------------------------------------------------------------
// fp32 SIMT GEMM C = A @ B^T for K/V projections
// ---------------------------------------------------------------------------
__global__ __launch_bounds__(256) void gemm_nt(
    const float* __restrict__ A, const float* __restrict__ Bt,
    float* __restrict__ C, int M, int N, int K)
{
    const int m0 = blockIdx.y * 128;
    const int n0 = blockIdx.x * 128;

    __shared__ float As[8][128];
    __shared__ float Bs[8][128];

    const int tid  = threadIdx.x;
    const int arow = tid >> 1;
    const int acol = (tid & 1) * 4;
    const int tr   = (tid >> 4) * 8;
    const int tc   = (tid & 15) * 8;

    float acc[8][8];
    #pragma unroll
    for (int i = 0; i < 8; i++)
        #pragma unroll
        for (int j = 0; j < 8; j++) acc[i][j] = 0.f;

    for (int k0 = 0; k0 < K; k0 += 8) {
        {
            const int gm = m0 + arow;
            float4 v = make_float4(0.f, 0.f, 0.f, 0.f);
            if (gm < M) v = *reinterpret_cast<const float4*>(A + (long)gm * K + k0 + acol);
            As[acol + 0][arow] = v.x; As[acol + 1][arow] = v.y;
            As[acol + 2][arow] = v.z; As[acol + 3][arow] = v.w;
        }
        {
            const int gn = n0 + arow;
            float4 v = make_float4(0.f, 0.f, 0.f, 0.f);
            if (gn < N) v = *reinterpret_cast<const float4*>(Bt + (long)gn * K + k0 + acol);
            Bs[acol + 0][arow] = v.x; Bs[acol + 1][arow] = v.y;
            Bs[acol + 2][arow] = v.z; Bs[acol + 3][arow] = v.w;
        }
        __syncthreads();
        #pragma unroll
        for (int kk = 0; kk < 8; kk++) {
            float ar[8], br[8];
            #pragma unroll
            for (int i = 0; i < 8; i++) ar[i] = As[kk][tr + i];
            #pragma unroll
            for (int j = 0; j < 8; j++) br[j] = Bs[kk][tc + j];
            #pragma unroll
            for (int i = 0; i < 8; i++)
                #pragma unroll
                for (int j = 0; j < 8; j++)
                    acc[i][j] = fmaf(ar[i], br[j], acc[i][j]);
        }
        __syncthreads();
    }
    #pragma unroll
    for (int i = 0; i < 8; i++) {
        const int gm = m0 + tr + i;
        if (gm >= M) continue;
        #pragma unroll
        for (int j = 0; j < 8; j++) {
            const int gn = n0 + tc + j;
            if (gn < N) C[(long)gm * N + gn] = acc[i][j];
        }
    }
}

// ---------------------------------------------------------------------------
// fold_A: AfoldT[b][h*77+t][c] (bf16 hi/lo) = d^-0.5 * sum_e wq[h*160+e][c]*K[b,t][h*160+e]
// ---------------------------------------------------------------------------
__global__ __launch_bounds__(256) void fold_A(
    const float* __restrict__ wq, const float* __restrict__ Kmat,
    __nv_bfloat16* __restrict__ outH, __nv_bfloat16* __restrict__ outL)
{
    const int b = blockIdx.z, hd = blockIdx.y;
    const int c0 = blockIdx.x * 128;
    __shared__ float Ws[16][128];
    __shared__ float Ks[16][80];

    const int tid  = threadIdx.x;
    const int tcid = tid & 15;
    const int ttid = tid >> 4;
    const float scale = 0.07905694150420949f;

    float acc[8][5];
    #pragma unroll
    for (int i = 0; i < 8; i++)
        #pragma unroll
        for (int j = 0; j < 5; j++) acc[i][j] = 0.f;

    for (int e0 = 0; e0 < DHEAD; e0 += 16) {
        {
            const int cc = (tid & 31) * 4;
            #pragma unroll
            for (int r = 0; r < 2; r++) {
                const int k = (tid >> 5) + r * 8;
                float4 v = *reinterpret_cast<const float4*>(
                    wq + (long)(hd * DHEAD + e0 + k) * DIM + c0 + cc);
                *reinterpret_cast<float4*>(&Ws[k][cc]) = v;
            }
        }
        for (int idx = tid; idx < TOK * 16; idx += 256) {
            const int t = idx >> 4, k = idx & 15;
            Ks[k][t] = Kmat[(long)(b * TOK + t) * DIM + hd * DHEAD + e0 + k];
        }
        for (int idx = tid; idx < 3 * 16; idx += 256)
            Ks[idx & 15][TOK + (idx >> 4)] = 0.f;
        __syncthreads();
        #pragma unroll
        for (int k = 0; k < 16; k++) {
            float w[8], kv[5];
            #pragma unroll
            for (int i = 0; i < 8; i++) w[i] = Ws[k][tcid * 8 + i];
            #pragma unroll
            for (int j = 0; j < 5; j++) kv[j] = Ks[k][ttid * 5 + j];
            #pragma unroll
            for (int i = 0; i < 8; i++)
                #pragma unroll
                for (int j = 0; j < 5; j++)
                    acc[i][j] = fmaf(w[i], kv[j], acc[i][j]);
        }
        __syncthreads();
    }
    #pragma unroll
    for (int i = 0; i < 8; i++) {
        const int c = c0 + tcid * 8 + i;
        #pragma unroll
        for (int j = 0; j < 5; j++) {
            const int t = ttid * 5 + j;
            if (t < TOK) {
                float val = acc[i][j] * scale;
                __nv_bfloat16 vh = __float2bfloat16(val);
                long off = ((long)b * JPAD + hd * TOK + t) * DIM + c;
                outH[off] = vh;
                outL[off] = __float2bfloat16(val - __bfloat162float(vh));
            }
        }
    }
}

// ---------------------------------------------------------------------------
// fold_B: B2T[b][e2][h*77+t] (bf16 hi/lo) = sum_e V[b,t][h*160+e]*wout[e2][h*160+e]
// ---------------------------------------------------------------------------
__global__ __launch_bounds__(256) void fold_B(
    const float* __restrict__ wout, const float* __restrict__ Vmat,
    __nv_bfloat16* __restrict__ outH, __nv_bfloat16* __restrict__ outL)
{
    const int b = blockIdx.z, hd = blockIdx.y;
    const int n0 = blockIdx.x * 128;
    __shared__ float Vs[16][80];
    __shared__ float Ws[16][128];

    const int tid  = threadIdx.x;
    const int tcid = tid & 15;
    const int ttid = tid >> 4;

    float acc[5][8];
    #pragma unroll
    for (int j = 0; j < 5; j++)
        #pragma unroll
        for (int i = 0; i < 8; i++) acc[j][i] = 0.f;

    for (int e0 = 0; e0 < DHEAD; e0 += 16) {
        for (int idx = tid; idx < 128 * 16; idx += 256) {
            const int n = idx >> 4, k = idx & 15;
            Ws[k][n] = wout[(long)(n0 + n) * DIM + hd * DHEAD + e0 + k];
        }
        for (int idx = tid; idx < TOK * 16; idx += 256) {
            const int t = idx >> 4, k = idx & 15;
            Vs[k][t] = Vmat[(long)(b * TOK + t) * DIM + hd * DHEAD + e0 + k];
        }
        for (int idx = tid; idx < 3 * 16; idx += 256)
            Vs[idx & 15][TOK + (idx >> 4)] = 0.f;
        __syncthreads();
        #pragma unroll
        for (int k = 0; k < 16; k++) {
            float vv[5], ww[8];
            #pragma unroll
            for (int j = 0; j < 5; j++) vv[j] = Vs[k][ttid * 5 + j];
            #pragma unroll
            for (int i = 0; i < 8; i++) ww[i] = Ws[k][tcid * 8 + i];
            #pragma unroll
            for (int j = 0; j < 5; j++)
                #pragma unroll
                for (int i = 0; i < 8; i++)
                    acc[j][i] = fmaf(vv[j], ww[i], acc[j][i]);
        }
        __syncthreads();
    }
    #pragma unroll
    for (int j = 0; j < 5; j++) {
        const int t = ttid * 5 + j;
        if (t >= TOK) continue;
        #pragma unroll
        for (int i = 0; i < 8; i++) {
            const int n = n0 + tcid * 8 + i;
            float val = acc[j][i];
            __nv_bfloat16 vh = __float2bfloat16(val);
            long off = ((long)b * DIM + n) * JPAD + hd * TOK + t;
            outH[off] = vh;
            outL[off] = __float2bfloat16(val - __bfloat162float(vh));
        }
    }
}

// ---------------------------------------------------------------------------
// zero the pad regions (AfoldT rows 616..639; B2T cols 616..639)
// ---------------------------------------------------------------------------
__global__ void zero_pads(__nv_bfloat16* Ah, __nv_bfloat16* Al,
                          __nv_bfloat16* Bh, __nv_bfloat16* Bl)
{
    const int PAD = JPAD - JDIM;               // 24
    const int n1 = BATCH * PAD * DIM;
    const int n2 = BATCH * DIM * PAD;
    const __nv_bfloat16 z = __float2bfloat16(0.f);
    for (int i = blockIdx.x * blockDim.x + threadIdx.x; i < n1 + n2;
         i += gridDim.x * blockDim.x) {
        if (i < n1) {
            int b = i / (PAD * DIM);
            int rem = i % (PAD * DIM);
            int r = rem / DIM, c = rem % DIM;
            long off = ((long)b * JPAD + JDIM + r) * DIM + c;
            Ah[off] = z; Al[off] = z;
        } else {
            int j = i - n1;
            int b = j / (DIM * PAD);
            int rem = j % (DIM * PAD);
            int e = rem / PAD, t = rem % PAD;
            long off = ((long)b * DIM + e) * JPAD + JDIM + t;
            Bh[off] = z; Bl[off] = z;
        }
    }
}

// ---------------------------------------------------------------------------
// fp32 -> bf16 hi/lo split
// ---------------------------------------------------------------------------
__global__ void split4(const float4* __restrict__ src,
                       __nv_bfloat162* __restrict__ h,
                       __nv_bfloat162* __restrict__ l, long n4)
{
    for (long i = (long)blockIdx.x * blockDim.x + threadIdx.x; i < n4;
         i += (long)gridDim.x * blockDim.x) {
        float4 v = src[i];
        __nv_bfloat162 h0 = __floats2bfloat162_rn(v.x, v.y);
        __nv_bfloat162 h1 = __floats2bfloat162_rn(v.z, v.w);
        __nv_bfloat162 l0 = __floats2bfloat162_rn(v.x - __low2float(h0),
                                                  v.y - __high2float(h0));
        __nv_bfloat162 l1 = __floats2bfloat162_rn(v.z - __low2float(h1),
                                                  v.w - __high2float(h1));
        h[2 * i]     = h0; h[2 * i + 1] = h1;
        l[2 * i]     = l0; l[2 * i + 1] = l1;
    }
}

// ---------------------------------------------------------------------------
// softmax over each 77-group (row stride JPAD); one warp per (row, head)
// ---------------------------------------------------------------------------
__global__ __launch_bounds__(256) void softmax77(float* __restrict__ Smat)
{
    const int gw   = blockIdx.x * 8 + (threadIdx.x >> 5);
    const int lane = threadIdx.x & 31;
    const long base = (long)(gw >> 3) * JPAD + (gw & 7) * TOK;

    const float NEG = -1e30f;
    float x0 = Smat[base + lane];
    float x1 = Smat[base + 32 + lane];
    float x2 = (lane < 13) ? Smat[base + 64 + lane] : NEG;

    float m = fmaxf(x0, fmaxf(x1, x2));
    #pragma unroll
    for (int o = 16; o > 0; o >>= 1)
        m = fmaxf(m, __shfl_xor_sync(0xffffffffu, m, o));

    float e0 = expf(x0 - m);
    float e1 = expf(x1 - m);
    float e2 = (lane < 13) ? expf(x2 - m) : 0.f;
    float s = e0 + e1 + e2;
    #pragma unroll
    for (int o = 16; o > 0; o >>= 1)
        s += __shfl_xor_sync(0xffffffffu, s, o);

    const float inv = 1.f / s;
    Smat[base + lane]      = e0 * inv;
    Smat[base + 32 + lane] = e1 * inv;
    if (lane < 13) Smat[base + 64 + lane] = e2 * inv;
}

// ---------------------------------------------------------------------------
extern "C" void kernel_launch(void* const* d_in, const int* in_sizes, int n_in,
                              void* d_out, int out_size)
{
    const float* X  = (const float*)d_in[0];
    const float* E  = (const float*)d_in[1];
    const float* wq = (const float*)d_in[2];
    const float* wk = (const float*)d_in[3];
    const float* wv = (const float*)d_in[4];
    const float* wo = (const float*)d_in[5];
    const float* bo = (const float*)d_in[6];
    float* out = (float*)d_out;

    float *pK, *pV, *pS;
    __nv_bfloat16 *pXh, *pXl, *pAh, *pAl, *pBh, *pBl, *pPh, *pPl;
    cudaGetSymbolAddress((void**)&pK,  g_K);
    cudaGetSymbolAddress((void**)&pV,  g_V);
    cudaGetSymbolAddress((void**)&pS,  g_S);
    cudaGetSymbolAddress((void**)&pXh, g_Xh);
    cudaGetSymbolAddress((void**)&pXl, g_Xl);
    cudaGetSymbolAddress((void**)&pAh, g_Ah);
    cudaGetSymbolAddress((void**)&pAl, g_Al);
    cudaGetSymbolAddress((void**)&pBh, g_Bh);
    cudaGetSymbolAddress((void**)&pBl, g_Bl);
    cudaGetSymbolAddress((void**)&pPh, g_Ph);
    cudaGetSymbolAddress((void**)&pPl, g_Pl);

    cudaFuncSetAttribute(mma_gemm, cudaFuncAttributeMaxDynamicSharedMemorySize,
                         MM_SMEM);

    // K/V projections (fp32 SIMT)
    gemm_nt<<<dim3(10, 10, 1), 256>>>(E, wk, pK, BATCH * TOK, DIM, CDIM);
    gemm_nt<<<dim3(10, 10, 1), 256>>>(E, wv, pV, BATCH * TOK, DIM, CDIM);

    // X split to bf16 hi/lo
    split4<<<8192, 256>>>((const float4*)X, (__nv_bfloat162*)pXh,
                          (__nv_bfloat162*)pXl, (long)BATCH * SEQ * DIM / 4);

    // folded operand matrices (bf16 hi/lo, K-major)
    fold_A<<<dim3(10, 8, 16), 256>>>(wq, pK, pAh, pAl);
    fold_B<<<dim3(10, 8, 16), 256>>>(wo, pV, pBh, pBl);
    zero_pads<<<2048, 256>>>(pAh, pAl, pBh, pBl);

    // scores: S[b][s][j] = sum_c X[s][c] * AfoldT[j][c]
    mma_gemm<<<dim3(JPAD / 128, SEQ / 128, BATCH), 256, MM_SMEM>>>(
        pXh, pXl, pAh, pAl, pS, nullptr, DIM, JPAD,
        (long)SEQ * DIM, (long)JPAD * DIM, (long)SEQ * JPAD);

    // softmax over 77-token groups
    softmax77<<<BATCH * SEQ, 256>>>(pS);

    // probs split to bf16 hi/lo
    split4<<<8192, 256>>>((const float4*)pS, (__nv_bfloat162*)pPh,
                          (__nv_bfloat162*)pPl, (long)BATCH * SEQ * JPAD / 4);

    // output: out[b][s][e] = sum_j P[s][j] * B2T[e][j] + bias[e]
    mma_gemm<<<dim3(DIM / 128, SEQ / 128, BATCH), 256, MM_SMEM>>>(
        pPh, pPl, pBh, pBl, out, bo, JPAD, DIM,
        (long)SEQ * JPAD, (long)DIM * JPAD, (long)SEQ * DIM);
}

// round 4
// speedup vs baseline: 2.9422x; 1.3267x over previous
#include <cuda_runtime.h>
#include <cuda_fp16.h>
#include <math.h>
#include <stdint.h>

#define BATCH 16
#define SEQ   4096
#define DIM   1280
#define TOK   77
#define CDIM  768
#define HEADS 8
#define DHEAD 160
#define JDIM  616
#define JPAD  640

// ---------------------------------------------------------------------------
// Scratch (static device globals)
// ---------------------------------------------------------------------------
__device__ __align__(256) float g_K [BATCH*TOK*DIM];
__device__ __align__(256) float g_V [BATCH*TOK*DIM];
__device__ __align__(256) float g_S [(size_t)BATCH*SEQ*JPAD];       // scores fp32
__device__ __align__(256) __half g_Xf[(size_t)BATCH*SEQ*DIM];       // X fp16
__device__ __align__(256) __half g_Ah[(size_t)BATCH*JPAD*DIM];      // AfoldT hi
__device__ __align__(256) __half g_Al[(size_t)BATCH*JPAD*DIM];      // AfoldT lo
__device__ __align__(256) __half g_Bh[(size_t)BATCH*DIM*JPAD];      // B2T hi
__device__ __align__(256) __half g_Bl[(size_t)BATCH*DIM*JPAD];      // B2T lo
__device__ __align__(256) __half g_P [(size_t)BATCH*SEQ*JPAD];      // probs fp16

// ---------------------------------------------------------------------------
// helpers
// ---------------------------------------------------------------------------
__device__ __forceinline__ uint32_t smem_u32(const void* p) {
    uint32_t a;
    asm("{ .reg .u64 t; cvta.to.shared.u64 t, %1; cvt.u32.u64 %0, t; }"
        : "=r"(a) : "l"(p));
    return a;
}

#define SWZ128(o) ((o) ^ (((o) >> 3) & 0x70))

__device__ __forceinline__ void cp16(uint32_t s, const void* g) {
    asm volatile("cp.async.cg.shared.global [%0], [%1], 16;" :: "r"(s), "l"(g));
}
#define CP_COMMIT() asm volatile("cp.async.commit_group;" ::: "memory")

__device__ __forceinline__ void ldsm4(uint32_t& r0, uint32_t& r1,
                                      uint32_t& r2, uint32_t& r3, uint32_t addr) {
    asm volatile("ldmatrix.sync.aligned.m8n8.x4.shared.b16 {%0,%1,%2,%3}, [%4];"
                 : "=r"(r0), "=r"(r1), "=r"(r2), "=r"(r3) : "r"(addr));
}

__device__ __forceinline__ void mma16816(float* c, uint32_t a0, uint32_t a1,
                                         uint32_t a2, uint32_t a3,
                                         uint32_t b0, uint32_t b1) {
    asm volatile(
        "mma.sync.aligned.m16n8k16.row.col.f32.f16.f16.f32 "
        "{%0,%1,%2,%3}, {%4,%5,%6,%7}, {%8,%9}, {%0,%1,%2,%3};"
        : "+f"(c[0]), "+f"(c[1]), "+f"(c[2]), "+f"(c[3])
        : "r"(a0), "r"(a1), "r"(a2), "r"(a3), "r"(b0), "r"(b1));
}

// ---------------------------------------------------------------------------
// warp-MMA GEMM:  C[m][n] = sum_k A[m][k]*(Bh[n][k]+Bl[n][k])   (fp16 2-pass)
// CTA tile 128x128, 8 warps (4M x 2N), warp tile 32x64.
// KC=64; stage = 3 tiles (A, Bh, Bl) of 128x64 fp16 = 48 KB; 3 stages.
// ---------------------------------------------------------------------------
#define KC 64
#define TILE_B 16384                     /* 128 rows x 128 bytes */
#define STAGE_B (3*TILE_B)               /* 48 KB */
#define NSTAGE 3
#define MM_SMEM (NSTAGE*STAGE_B)         /* 144 KB */

__global__ __launch_bounds__(256, 1)
void mma_gemm(const __half* __restrict__ A,
              const __half* __restrict__ Bh, const __half* __restrict__ Bl,
              float* __restrict__ C, const float* __restrict__ bias,
              int K, int ldc, long sA, long sB, long sC)
{
    extern __shared__ __align__(1024) char smem[];
    const uint32_t sbase = smem_u32(smem);
    const int tid  = threadIdx.x;
    const int wid  = tid >> 5;
    const int lane = tid & 31;
    const int wm   = wid & 3;            // 0..3 : M slice of 32
    const int wn   = wid >> 2;           // 0..1 : N slice of 64

    const long rowA = (long)blockIdx.z * sA + (long)(blockIdx.y * 128) * K;
    const long rowB = (long)blockIdx.z * sB + (long)(blockIdx.x * 128) * K;

    // ---- per-thread cp.async slots: 3072 16B units across 3 tiles ----
    uint32_t soff[12];
    const char* gp[12];
    #pragma unroll
    for (int i = 0; i < 12; ++i) {
        int idx = tid + i * 256;
        int t = idx >> 10;               // 0:A 1:Bh 2:Bl
        int r = (idx >> 3) & 127;
        int u = idx & 7;
        soff[i] = (uint32_t)(t * TILE_B) + SWZ128((uint32_t)(r * 128 + u * 16));
        const __half* base =
            (t == 0) ? (A + rowA) : (t == 1) ? (Bh + rowB) : (Bl + rowB);
        gp[i] = (const char*)(base + (long)r * K + u * 8);
    }

    // ---- ldmatrix address pre-computation ----
    uint32_t aRowOff[2], aXor[2];
    #pragma unroll
    for (int mi = 0; mi < 2; ++mi) {
        int r = wm * 32 + mi * 16 + (lane & 15);
        aRowOff[mi] = (uint32_t)(r * 128);
        aXor[mi]    = (uint32_t)((r & 7) * 16);
    }
    const uint32_t aG = (uint32_t)((lane >> 4) * 16);

    uint32_t bRowOff[4], bXor[4];
    #pragma unroll
    for (int q = 0; q < 4; ++q) {
        int r = wn * 64 + q * 16 + (lane & 7) + ((lane >> 4) << 3);
        bRowOff[q] = (uint32_t)(r * 128);
        bXor[q]    = (uint32_t)((r & 7) * 16);
    }
    const uint32_t bG = (uint32_t)(((lane >> 3) & 1) * 16);

    float acc[2][8][4];
    #pragma unroll
    for (int mi = 0; mi < 2; ++mi)
        #pragma unroll
        for (int ni = 0; ni < 8; ++ni)
            #pragma unroll
            for (int e = 0; e < 4; ++e) acc[mi][ni][e] = 0.f;

    const int nk = K / KC;

    // prologue: chunks 0,1 -> stages 0,1
    #pragma unroll
    for (int i = 0; i < 12; ++i) cp16(sbase + soff[i], gp[i]);
    CP_COMMIT();
    #pragma unroll
    for (int i = 0; i < 12; ++i) gp[i] += 128;
    {
        const uint32_t sb = sbase + STAGE_B;
        #pragma unroll
        for (int i = 0; i < 12; ++i) cp16(sb + soff[i], gp[i]);
        CP_COMMIT();
        #pragma unroll
        for (int i = 0; i < 12; ++i) gp[i] += 128;
    }

    for (int k = 0; k < nk; ++k) {
        if (k + 2 < nk) {
            const uint32_t sb = sbase + ((k + 2) % NSTAGE) * STAGE_B;
            #pragma unroll
            for (int i = 0; i < 12; ++i) cp16(sb + soff[i], gp[i]);
            CP_COMMIT();
            #pragma unroll
            for (int i = 0; i < 12; ++i) gp[i] += 128;
            asm volatile("cp.async.wait_group 2;" ::: "memory");
        } else if (k + 1 < nk) {
            asm volatile("cp.async.wait_group 1;" ::: "memory");
        } else {
            asm volatile("cp.async.wait_group 0;" ::: "memory");
        }
        __syncthreads();

        const uint32_t st = sbase + (k % NSTAGE) * STAGE_B;
        const uint32_t aT  = st;
        const uint32_t bhT = st + TILE_B;
        const uint32_t blT = st + 2 * TILE_B;
        #pragma unroll
        for (int kk = 0; kk < 4; ++kk) {
            const uint32_t kb = (uint32_t)(kk * 32);
            uint32_t a[2][4];
            #pragma unroll
            for (int mi = 0; mi < 2; ++mi)
                ldsm4(a[mi][0], a[mi][1], a[mi][2], a[mi][3],
                      aT + aRowOff[mi] + ((aG + kb) ^ aXor[mi]));
            uint32_t bh[4][4], bl[4][4];
            #pragma unroll
            for (int q = 0; q < 4; ++q)
                ldsm4(bh[q][0], bh[q][1], bh[q][2], bh[q][3],
                      bhT + bRowOff[q] + ((bG + kb) ^ bXor[q]));
            #pragma unroll
            for (int q = 0; q < 4; ++q)
                ldsm4(bl[q][0], bl[q][1], bl[q][2], bl[q][3],
                      blT + bRowOff[q] + ((bG + kb) ^ bXor[q]));
            #pragma unroll
            for (int mi = 0; mi < 2; ++mi)
                #pragma unroll
                for (int q = 0; q < 4; ++q) {
                    mma16816(acc[mi][q * 2 + 0],
                             a[mi][0], a[mi][1], a[mi][2], a[mi][3],
                             bh[q][0], bh[q][1]);
                    mma16816(acc[mi][q * 2 + 1],
                             a[mi][0], a[mi][1], a[mi][2], a[mi][3],
                             bh[q][2], bh[q][3]);
                }
            #pragma unroll
            for (int mi = 0; mi < 2; ++mi)
                #pragma unroll
                for (int q = 0; q < 4; ++q) {
                    mma16816(acc[mi][q * 2 + 0],
                             a[mi][0], a[mi][1], a[mi][2], a[mi][3],
                             bl[q][0], bl[q][1]);
                    mma16816(acc[mi][q * 2 + 1],
                             a[mi][0], a[mi][1], a[mi][2], a[mi][3],
                             bl[q][2], bl[q][3]);
                }
        }
        __syncthreads();
    }

    // ---- epilogue ----
    const int row0 = blockIdx.y * 128 + wm * 32 + (lane >> 2);
    const int col0 = blockIdx.x * 128 + wn * 64 + (lane & 3) * 2;
    float* Cb = C + (long)blockIdx.z * sC;
    #pragma unroll
    for (int mi = 0; mi < 2; ++mi) {
        #pragma unroll
        for (int ni = 0; ni < 8; ++ni) {
            const int r = row0 + mi * 16;
            const int c = col0 + ni * 8;
            float bx = 0.f, by = 0.f;
            if (bias) { bx = bias[c]; by = bias[c + 1]; }
            float2 v0 = make_float2(acc[mi][ni][0] + bx, acc[mi][ni][1] + by);
            float2 v1 = make_float2(acc[mi][ni][2] + bx, acc[mi][ni][3] + by);
            *reinterpret_cast<float2*>(Cb + (long)r * ldc + c)       = v0;
            *reinterpret_cast<float2*>(Cb + (long)(r + 8) * ldc + c) = v1;
        }
    }
}

// ---------------------------------------------------------------------------
// fp32 SIMT GEMM C = A @ B^T for K/V projections
// ---------------------------------------------------------------------------
__global__ __launch_bounds__(256) void gemm_nt(
    const float* __restrict__ A, const float* __restrict__ Bt,
    float* __restrict__ C, int M, int N, int K)
{
    const int m0 = blockIdx.y * 128;
    const int n0 = blockIdx.x * 128;

    __shared__ float As[8][128];
    __shared__ float Bs[8][128];

    const int tid  = threadIdx.x;
    const int arow = tid >> 1;
    const int acol = (tid & 1) * 4;
    const int tr   = (tid >> 4) * 8;
    const int tc   = (tid & 15) * 8;

    float acc[8][8];
    #pragma unroll
    for (int i = 0; i < 8; i++)
        #pragma unroll
        for (int j = 0; j < 8; j++) acc[i][j] = 0.f;

    for (int k0 = 0; k0 < K; k0 += 8) {
        {
            const int gm = m0 + arow;
            float4 v = make_float4(0.f, 0.f, 0.f, 0.f);
            if (gm < M) v = *reinterpret_cast<const float4*>(A + (long)gm * K + k0 + acol);
            As[acol + 0][arow] = v.x; As[acol + 1][arow] = v.y;
            As[acol + 2][arow] = v.z; As[acol + 3][arow] = v.w;
        }
        {
            const int gn = n0 + arow;
            float4 v = make_float4(0.f, 0.f, 0.f, 0.f);
            if (gn < N) v = *reinterpret_cast<const float4*>(Bt + (long)gn * K + k0 + acol);
            Bs[acol + 0][arow] = v.x; Bs[acol + 1][arow] = v.y;
            Bs[acol + 2][arow] = v.z; Bs[acol + 3][arow] = v.w;
        }
        __syncthreads();
        #pragma unroll
        for (int kk = 0; kk < 8; kk++) {
            float ar[8], br[8];
            #pragma unroll
            for (int i = 0; i < 8; i++) ar[i] = As[kk][tr + i];
            #pragma unroll
            for (int j = 0; j < 8; j++) br[j] = Bs[kk][tc + j];
            #pragma unroll
            for (int i = 0; i < 8; i++)
                #pragma unroll
                for (int j = 0; j < 8; j++)
                    acc[i][j] = fmaf(ar[i], br[j], acc[i][j]);
        }
        __syncthreads();
    }
    #pragma unroll
    for (int i = 0; i < 8; i++) {
        const int gm = m0 + tr + i;
        if (gm >= M) continue;
        #pragma unroll
        for (int j = 0; j < 8; j++) {
            const int gn = n0 + tc + j;
            if (gn < N) C[(long)gm * N + gn] = acc[i][j];
        }
    }
}

// ---------------------------------------------------------------------------
// fold_A: AfoldT[b][h*77+t][c] (fp16 hi/lo) = d^-0.5 * sum_e wq[h*160+e][c]*K[b,t][h*160+e]
// ---------------------------------------------------------------------------
__global__ __launch_bounds__(256) void fold_A(
    const float* __restrict__ wq, const float* __restrict__ Kmat,
    __half* __restrict__ outH, __half* __restrict__ outL)
{
    const int b = blockIdx.z, hd = blockIdx.y;
    const int c0 = blockIdx.x * 128;
    __shared__ float Ws[16][128];
    __shared__ float Ks[16][80];

    const int tid  = threadIdx.x;
    const int tcid = tid & 15;
    const int ttid = tid >> 4;
    const float scale = 0.07905694150420949f;

    float acc[8][5];
    #pragma unroll
    for (int i = 0; i < 8; i++)
        #pragma unroll
        for (int j = 0; j < 5; j++) acc[i][j] = 0.f;

    for (int e0 = 0; e0 < DHEAD; e0 += 16) {
        {
            const int cc = (tid & 31) * 4;
            #pragma unroll
            for (int r = 0; r < 2; r++) {
                const int k = (tid >> 5) + r * 8;
                float4 v = *reinterpret_cast<const float4*>(
                    wq + (long)(hd * DHEAD + e0 + k) * DIM + c0 + cc);
                *reinterpret_cast<float4*>(&Ws[k][cc]) = v;
            }
        }
        for (int idx = tid; idx < TOK * 16; idx += 256) {
            const int t = idx >> 4, k = idx & 15;
            Ks[k][t] = Kmat[(long)(b * TOK + t) * DIM + hd * DHEAD + e0 + k];
        }
        for (int idx = tid; idx < 3 * 16; idx += 256)
            Ks[idx & 15][TOK + (idx >> 4)] = 0.f;
        __syncthreads();
        #pragma unroll
        for (int k = 0; k < 16; k++) {
            float w[8], kv[5];
            #pragma unroll
            for (int i = 0; i < 8; i++) w[i] = Ws[k][tcid * 8 + i];
            #pragma unroll
            for (int j = 0; j < 5; j++) kv[j] = Ks[k][ttid * 5 + j];
            #pragma unroll
            for (int i = 0; i < 8; i++)
                #pragma unroll
                for (int j = 0; j < 5; j++)
                    acc[i][j] = fmaf(w[i], kv[j], acc[i][j]);
        }
        __syncthreads();
    }
    #pragma unroll
    for (int i = 0; i < 8; i++) {
        const int c = c0 + tcid * 8 + i;
        #pragma unroll
        for (int j = 0; j < 5; j++) {
            const int t = ttid * 5 + j;
            if (t < TOK) {
                float val = acc[i][j] * scale;
                __half vh = __float2half_rn(val);
                long off = ((long)b * JPAD + hd * TOK + t) * DIM + c;
                outH[off] = vh;
                outL[off] = __float2half_rn(val - __half2float(vh));
            }
        }
    }
}

// ---------------------------------------------------------------------------
// fold_B: B2T[b][e2][h*77+t] (fp16 hi/lo) = sum_e V[b,t][h*160+e]*wout[e2][h*160+e]
// ---------------------------------------------------------------------------
__global__ __launch_bounds__(256) void fold_B(
    const float* __restrict__ wout, const float* __restrict__ Vmat,
    __half* __restrict__ outH, __half* __restrict__ outL)
{
    const int b = blockIdx.z, hd = blockIdx.y;
    const int n0 = blockIdx.x * 128;
    __shared__ float Vs[16][80];
    __shared__ float Ws[16][128];

    const int tid  = threadIdx.x;
    const int tcid = tid & 15;
    const int ttid = tid >> 4;

    float acc[5][8];
    #pragma unroll
    for (int j = 0; j < 5; j++)
        #pragma unroll
        for (int i = 0; i < 8; i++) acc[j][i] = 0.f;

    for (int e0 = 0; e0 < DHEAD; e0 += 16) {
        for (int idx = tid; idx < 128 * 16; idx += 256) {
            const int n = idx >> 4, k = idx & 15;
            Ws[k][n] = wout[(long)(n0 + n) * DIM + hd * DHEAD + e0 + k];
        }
        for (int idx = tid; idx < TOK * 16; idx += 256) {
            const int t = idx >> 4, k = idx & 15;
            Vs[k][t] = Vmat[(long)(b * TOK + t) * DIM + hd * DHEAD + e0 + k];
        }
        for (int idx = tid; idx < 3 * 16; idx += 256)
            Vs[idx & 15][TOK + (idx >> 4)] = 0.f;
        __syncthreads();
        #pragma unroll
        for (int k = 0; k < 16; k++) {
            float vv[5], ww[8];
            #pragma unroll
            for (int j = 0; j < 5; j++) vv[j] = Vs[k][ttid * 5 + j];
            #pragma unroll
            for (int i = 0; i < 8; i++) ww[i] = Ws[k][tcid * 8 + i];
            #pragma unroll
            for (int j = 0; j < 5; j++)
                #pragma unroll
                for (int i = 0; i < 8; i++)
                    acc[j][i] = fmaf(vv[j], ww[i], acc[j][i]);
        }
        __syncthreads();
    }
    #pragma unroll
    for (int j = 0; j < 5; j++) {
        const int t = ttid * 5 + j;
        if (t >= TOK) continue;
        #pragma unroll
        for (int i = 0; i < 8; i++) {
            const int n = n0 + tcid * 8 + i;
            float val = acc[j][i];
            __half vh = __float2half_rn(val);
            long off = ((long)b * DIM + n) * JPAD + hd * TOK + t;
            outH[off] = vh;
            outL[off] = __float2half_rn(val - __half2float(vh));
        }
    }
}

// ---------------------------------------------------------------------------
// zero pads (AfoldT rows 616..639; B2T cols 616..639)
// ---------------------------------------------------------------------------
__global__ void zero_pads(__half* Ah, __half* Al, __half* Bh, __half* Bl)
{
    const int PAD = JPAD - JDIM;               // 24
    const int n1 = BATCH * PAD * DIM;
    const int n2 = BATCH * DIM * PAD;
    const __half z = __float2half_rn(0.f);
    for (int i = blockIdx.x * blockDim.x + threadIdx.x; i < n1 + n2;
         i += gridDim.x * blockDim.x) {
        if (i < n1) {
            int b = i / (PAD * DIM);
            int rem = i % (PAD * DIM);
            int r = rem / DIM, c = rem % DIM;
            long off = ((long)b * JPAD + JDIM + r) * DIM + c;
            Ah[off] = z; Al[off] = z;
        } else {
            int j = i - n1;
            int b = j / (DIM * PAD);
            int rem = j % (DIM * PAD);
            int e = rem / PAD, t = rem % PAD;
            long off = ((long)b * DIM + e) * JPAD + JDIM + t;
            Bh[off] = z; Bl[off] = z;
        }
    }
}

// ---------------------------------------------------------------------------
// fp32 -> fp16 convert (X)
// ---------------------------------------------------------------------------
__global__ void cvt_h4(const float4* __restrict__ src,
                       __half2* __restrict__ dst, long n4)
{
    for (long i = (long)blockIdx.x * blockDim.x + threadIdx.x; i < n4;
         i += (long)gridDim.x * blockDim.x) {
        float4 v = src[i];
        dst[2 * i]     = __floats2half2_rn(v.x, v.y);
        dst[2 * i + 1] = __floats2half2_rn(v.z, v.w);
    }
}

// ---------------------------------------------------------------------------
// fused softmax(77-group) -> fp16 probs; also zeros prob pad cols
// ---------------------------------------------------------------------------
__global__ __launch_bounds__(256) void softmax77h(const float* __restrict__ Smat,
                                                  __half* __restrict__ P)
{
    const int gw   = blockIdx.x * 8 + (threadIdx.x >> 5);
    const int lane = threadIdx.x & 31;
    const int row  = gw >> 3;
    const int h    = gw & 7;
    const long base = (long)row * JPAD + h * TOK;

    const float NEG = -1e30f;
    float x0 = Smat[base + lane];
    float x1 = Smat[base + 32 + lane];
    float x2 = (lane < 13) ? Smat[base + 64 + lane] : NEG;

    float m = fmaxf(x0, fmaxf(x1, x2));
    #pragma unroll
    for (int o = 16; o > 0; o >>= 1)
        m = fmaxf(m, __shfl_xor_sync(0xffffffffu, m, o));

    float e0 = expf(x0 - m);
    float e1 = expf(x1 - m);
    float e2 = (lane < 13) ? expf(x2 - m) : 0.f;
    float s = e0 + e1 + e2;
    #pragma unroll
    for (int o = 16; o > 0; o >>= 1)
        s += __shfl_xor_sync(0xffffffffu, s, o);

    const float inv = 1.f / s;
    P[base + lane]      = __float2half_rn(e0 * inv);
    P[base + 32 + lane] = __float2half_rn(e1 * inv);
    if (lane < 13) P[base + 64 + lane] = __float2half_rn(e2 * inv);
    // zero pad cols 616..639 (head-7 warp)
    if (h == 7 && lane < JPAD - JDIM)
        P[(long)row * JPAD + JDIM + lane] = __float2half_rn(0.f);
}

// ---------------------------------------------------------------------------
extern "C" void kernel_launch(void* const* d_in, const int* in_sizes, int n_in,
                              void* d_out, int out_size)
{
    const float* X  = (const float*)d_in[0];
    const float* E  = (const float*)d_in[1];
    const float* wq = (const float*)d_in[2];
    const float* wk = (const float*)d_in[3];
    const float* wv = (const float*)d_in[4];
    const float* wo = (const float*)d_in[5];
    const float* bo = (const float*)d_in[6];
    float* out = (float*)d_out;

    float *pK, *pV, *pS;
    __half *pXf, *pAh, *pAl, *pBh, *pBl, *pP;
    cudaGetSymbolAddress((void**)&pK,  g_K);
    cudaGetSymbolAddress((void**)&pV,  g_V);
    cudaGetSymbolAddress((void**)&pS,  g_S);
    cudaGetSymbolAddress((void**)&pXf, g_Xf);
    cudaGetSymbolAddress((void**)&pAh, g_Ah);
    cudaGetSymbolAddress((void**)&pAl, g_Al);
    cudaGetSymbolAddress((void**)&pBh, g_Bh);
    cudaGetSymbolAddress((void**)&pBl, g_Bl);
    cudaGetSymbolAddress((void**)&pP,  g_P);

    cudaFuncSetAttribute(mma_gemm, cudaFuncAttributeMaxDynamicSharedMemorySize,
                         MM_SMEM);

    // K/V projections (fp32 SIMT)
    gemm_nt<<<dim3(10, 10, 1), 256>>>(E, wk, pK, BATCH * TOK, DIM, CDIM);
    gemm_nt<<<dim3(10, 10, 1), 256>>>(E, wv, pV, BATCH * TOK, DIM, CDIM);

    // X -> fp16
    cvt_h4<<<8192, 256>>>((const float4*)X, (__half2*)pXf,
                          (long)BATCH * SEQ * DIM / 4);

    // folded operand matrices (fp16 hi/lo, K-major)
    fold_A<<<dim3(10, 8, 16), 256>>>(wq, pK, pAh, pAl);
    fold_B<<<dim3(10, 8, 16), 256>>>(wo, pV, pBh, pBl);
    zero_pads<<<2048, 256>>>(pAh, pAl, pBh, pBl);

    // scores: S[b][s][j] = sum_c X[s][c] * AfoldT[j][c]
    mma_gemm<<<dim3(JPAD / 128, SEQ / 128, BATCH), 256, MM_SMEM>>>(
        pXf, pAh, pAl, pS, nullptr, DIM, JPAD,
        (long)SEQ * DIM, (long)JPAD * DIM, (long)SEQ * JPAD);

    // fused softmax -> fp16 probs
    softmax77h<<<BATCH * SEQ, 256>>>(pS, pP);

    // output: out[b][s][e] = sum_j P[s][j] * B2T[e][j] + bias[e]
    mma_gemm<<<dim3(DIM / 128, SEQ / 128, BATCH), 256, MM_SMEM>>>(
        pP, pBh, pBl, out, bo, JPAD, DIM,
        (long)SEQ * JPAD, (long)DIM * JPAD, (long)SEQ * DIM);
}

// round 5
// speedup vs baseline: 4.1975x; 1.4266x over previous
#include <cuda_runtime.h>
#include <cuda_fp16.h>
#include <math.h>
#include <stdint.h>

#define BATCH 16
#define SEQ   4096
#define DIM   1280
#define TOK   77
#define CDIM  768
#define HEADS 8
#define DHEAD 160
#define JDIM  616
#define JPAD  640

// ---------------------------------------------------------------------------
// Scratch (static device globals)
// ---------------------------------------------------------------------------
__device__ __align__(256) float g_K [BATCH*TOK*DIM];
__device__ __align__(256) float g_V [BATCH*TOK*DIM];
__device__ __align__(256) float g_S [(size_t)BATCH*SEQ*JPAD];       // scores fp32
__device__ __align__(256) __half g_Xf[(size_t)BATCH*SEQ*DIM];       // X fp16
__device__ __align__(256) __half g_A [(size_t)BATCH*JPAD*DIM];      // AfoldT fp16
__device__ __align__(256) __half g_B2[(size_t)BATCH*DIM*JPAD];      // B2T fp16
__device__ __align__(256) __half g_P [(size_t)BATCH*SEQ*JPAD];      // probs fp16

// ---------------------------------------------------------------------------
// helpers
// ---------------------------------------------------------------------------
__device__ __forceinline__ uint32_t smem_u32(const void* p) {
    uint32_t a;
    asm("{ .reg .u64 t; cvta.to.shared.u64 t, %1; cvt.u32.u64 %0, t; }"
        : "=r"(a) : "l"(p));
    return a;
}

#define SWZ128(o) ((o) ^ (((o) >> 3) & 0x70))

__device__ __forceinline__ void cp16(uint32_t s, const void* g) {
    asm volatile("cp.async.cg.shared.global [%0], [%1], 16;" :: "r"(s), "l"(g));
}
#define CP_COMMIT() asm volatile("cp.async.commit_group;" ::: "memory")

__device__ __forceinline__ void ldsm4(uint32_t& r0, uint32_t& r1,
                                      uint32_t& r2, uint32_t& r3, uint32_t addr) {
    asm volatile("ldmatrix.sync.aligned.m8n8.x4.shared.b16 {%0,%1,%2,%3}, [%4];"
                 : "=r"(r0), "=r"(r1), "=r"(r2), "=r"(r3) : "r"(addr));
}

__device__ __forceinline__ void mma16816(float* c, uint32_t a0, uint32_t a1,
                                         uint32_t a2, uint32_t a3,
                                         uint32_t b0, uint32_t b1) {
    asm volatile(
        "mma.sync.aligned.m16n8k16.row.col.f32.f16.f16.f32 "
        "{%0,%1,%2,%3}, {%4,%5,%6,%7}, {%8,%9}, {%0,%1,%2,%3};"
        : "+f"(c[0]), "+f"(c[1]), "+f"(c[2]), "+f"(c[3])
        : "r"(a0), "r"(a1), "r"(a2), "r"(a3), "r"(b0), "r"(b1));
}

// ---------------------------------------------------------------------------
// warp-MMA GEMM:  C[m][n] = sum_k A[m][k]*B[n][k]   (single-pass fp16)
// CTA tile 128x128, 8 warps (4M x 2N), warp tile 32x64.
// KC=64; stage = 2 tiles (A, B) of 128x64 fp16 = 32 KB; 3 stages = 96 KB.
// 2 CTAs / SM.
// ---------------------------------------------------------------------------
#define KC 64
#define TILE_B 16384                     /* 128 rows x 128 bytes */
#define STAGE_B (2*TILE_B)               /* 32 KB */
#define NSTAGE 3
#define MM_SMEM (NSTAGE*STAGE_B)         /* 96 KB */

__global__ __launch_bounds__(256, 2)
void mma_gemm(const __half* __restrict__ A, const __half* __restrict__ B,
              float* __restrict__ C, const float* __restrict__ bias,
              int K, int ldc, long sA, long sB, long sC)
{
    extern __shared__ __align__(1024) char smem[];
    const uint32_t sbase = smem_u32(smem);
    const int tid  = threadIdx.x;
    const int wid  = tid >> 5;
    const int lane = tid & 31;
    const int wm   = wid & 3;            // 0..3 : M slice of 32
    const int wn   = wid >> 2;           // 0..1 : N slice of 64

    const char* baseA = (const char*)(A + (long)blockIdx.z * sA
                                        + (long)(blockIdx.y * 128) * K);
    const char* baseB = (const char*)(B + (long)blockIdx.z * sB
                                        + (long)(blockIdx.x * 128) * K);

    // ---- cp.async slots: 4 per tile per thread (1024 16B units per tile) ----
    // slot i covers idx = tid + i*256; r = (idx>>3)&127, u = idx&7.
    // A and B share the same (r,u) -> same goff, soff; B adds TILE_B.
    uint32_t soff[4], goff[4];
    #pragma unroll
    for (int i = 0; i < 4; ++i) {
        int idx = tid + i * 256;
        int r = (idx >> 3) & 127;
        int u = idx & 7;
        soff[i] = SWZ128((uint32_t)(r * 128 + u * 16));
        goff[i] = (uint32_t)(r * (K * 2) + u * 16);
    }

    // ---- ldmatrix address pre-computation ----
    uint32_t aRowOff[2], aXor[2];
    #pragma unroll
    for (int mi = 0; mi < 2; ++mi) {
        int r = wm * 32 + mi * 16 + (lane & 15);
        aRowOff[mi] = (uint32_t)(r * 128);
        aXor[mi]    = (uint32_t)((r & 7) * 16);
    }
    const uint32_t aG = (uint32_t)((lane >> 4) * 16);

    uint32_t bRowOff[4], bXor[4];
    #pragma unroll
    for (int q = 0; q < 4; ++q) {
        int r = wn * 64 + q * 16 + (lane & 7) + ((lane >> 4) << 3);
        bRowOff[q] = (uint32_t)(r * 128);
        bXor[q]    = (uint32_t)((r & 7) * 16);
    }
    const uint32_t bG = (uint32_t)(((lane >> 3) & 1) * 16);

    float acc[2][8][4];
    #pragma unroll
    for (int mi = 0; mi < 2; ++mi)
        #pragma unroll
        for (int ni = 0; ni < 8; ++ni)
            #pragma unroll
            for (int e = 0; e < 4; ++e) acc[mi][ni][e] = 0.f;

    const int nk = K / KC;

    // prologue: chunks 0,1 -> stages 0,1
    #pragma unroll
    for (int i = 0; i < 4; ++i) {
        cp16(sbase + soff[i],          baseA + goff[i]);
        cp16(sbase + TILE_B + soff[i], baseB + goff[i]);
    }
    CP_COMMIT();
    #pragma unroll
    for (int i = 0; i < 4; ++i) {
        cp16(sbase + STAGE_B + soff[i],          baseA + goff[i] + 128);
        cp16(sbase + STAGE_B + TILE_B + soff[i], baseB + goff[i] + 128);
    }
    CP_COMMIT();
    #pragma unroll
    for (int i = 0; i < 4; ++i) goff[i] += 256;

    for (int k = 0; k < nk; ++k) {
        if (k + 2 < nk) {
            const uint32_t sb = sbase + ((k + 2) % NSTAGE) * STAGE_B;
            #pragma unroll
            for (int i = 0; i < 4; ++i) {
                cp16(sb + soff[i],          baseA + goff[i]);
                cp16(sb + TILE_B + soff[i], baseB + goff[i]);
            }
            CP_COMMIT();
            #pragma unroll
            for (int i = 0; i < 4; ++i) goff[i] += 128;
            asm volatile("cp.async.wait_group 2;" ::: "memory");
        } else if (k + 1 < nk) {
            asm volatile("cp.async.wait_group 1;" ::: "memory");
        } else {
            asm volatile("cp.async.wait_group 0;" ::: "memory");
        }
        __syncthreads();

        const uint32_t aT = sbase + (k % NSTAGE) * STAGE_B;
        const uint32_t bT = aT + TILE_B;
        #pragma unroll
        for (int kk = 0; kk < 4; ++kk) {
            const uint32_t kb = (uint32_t)(kk * 32);
            uint32_t a[2][4];
            #pragma unroll
            for (int mi = 0; mi < 2; ++mi)
                ldsm4(a[mi][0], a[mi][1], a[mi][2], a[mi][3],
                      aT + aRowOff[mi] + ((aG + kb) ^ aXor[mi]));
            uint32_t b[4][4];
            #pragma unroll
            for (int q = 0; q < 4; ++q)
                ldsm4(b[q][0], b[q][1], b[q][2], b[q][3],
                      bT + bRowOff[q] + ((bG + kb) ^ bXor[q]));
            #pragma unroll
            for (int mi = 0; mi < 2; ++mi)
                #pragma unroll
                for (int q = 0; q < 4; ++q) {
                    mma16816(acc[mi][q * 2 + 0],
                             a[mi][0], a[mi][1], a[mi][2], a[mi][3],
                             b[q][0], b[q][1]);
                    mma16816(acc[mi][q * 2 + 1],
                             a[mi][0], a[mi][1], a[mi][2], a[mi][3],
                             b[q][2], b[q][3]);
                }
        }
        __syncthreads();
    }

    // ---- epilogue ----
    const int row0 = blockIdx.y * 128 + wm * 32 + (lane >> 2);
    const int col0 = blockIdx.x * 128 + wn * 64 + (lane & 3) * 2;
    float* Cb = C + (long)blockIdx.z * sC;
    #pragma unroll
    for (int mi = 0; mi < 2; ++mi) {
        #pragma unroll
        for (int ni = 0; ni < 8; ++ni) {
            const int r = row0 + mi * 16;
            const int c = col0 + ni * 8;
            float bx = 0.f, by = 0.f;
            if (bias) { bx = bias[c]; by = bias[c + 1]; }
            float2 v0 = make_float2(acc[mi][ni][0] + bx, acc[mi][ni][1] + by);
            float2 v1 = make_float2(acc[mi][ni][2] + bx, acc[mi][ni][3] + by);
            *reinterpret_cast<float2*>(Cb + (long)r * ldc + c)       = v0;
            *reinterpret_cast<float2*>(Cb + (long)(r + 8) * ldc + c) = v1;
        }
    }
}

// ---------------------------------------------------------------------------
// fp32 SIMT GEMM C = A @ B^T for K/V projections
// ---------------------------------------------------------------------------
__global__ __launch_bounds__(256) void gemm_nt(
    const float* __restrict__ A, const float* __restrict__ Bt,
    float* __restrict__ C, int M, int N, int K)
{
    const int m0 = blockIdx.y * 128;
    const int n0 = blockIdx.x * 128;

    __shared__ float As[8][128];
    __shared__ float Bs[8][128];

    const int tid  = threadIdx.x;
    const int arow = tid >> 1;
    const int acol = (tid & 1) * 4;
    const int tr   = (tid >> 4) * 8;
    const int tc   = (tid & 15) * 8;

    float acc[8][8];
    #pragma unroll
    for (int i = 0; i < 8; i++)
        #pragma unroll
        for (int j = 0; j < 8; j++) acc[i][j] = 0.f;

    for (int k0 = 0; k0 < K; k0 += 8) {
        {
            const int gm = m0 + arow;
            float4 v = make_float4(0.f, 0.f, 0.f, 0.f);
            if (gm < M) v = *reinterpret_cast<const float4*>(A + (long)gm * K + k0 + acol);
            As[acol + 0][arow] = v.x; As[acol + 1][arow] = v.y;
            As[acol + 2][arow] = v.z; As[acol + 3][arow] = v.w;
        }
        {
            const int gn = n0 + arow;
            float4 v = make_float4(0.f, 0.f, 0.f, 0.f);
            if (gn < N) v = *reinterpret_cast<const float4*>(Bt + (long)gn * K + k0 + acol);
            Bs[acol + 0][arow] = v.x; Bs[acol + 1][arow] = v.y;
            Bs[acol + 2][arow] = v.z; Bs[acol + 3][arow] = v.w;
        }
        __syncthreads();
        #pragma unroll
        for (int kk = 0; kk < 8; kk++) {
            float ar[8], br[8];
            #pragma unroll
            for (int i = 0; i < 8; i++) ar[i] = As[kk][tr + i];
            #pragma unroll
            for (int j = 0; j < 8; j++) br[j] = Bs[kk][tc + j];
            #pragma unroll
            for (int i = 0; i < 8; i++)
                #pragma unroll
                for (int j = 0; j < 8; j++)
                    acc[i][j] = fmaf(ar[i], br[j], acc[i][j]);
        }
        __syncthreads();
    }
    #pragma unroll
    for (int i = 0; i < 8; i++) {
        const int gm = m0 + tr + i;
        if (gm >= M) continue;
        #pragma unroll
        for (int j = 0; j < 8; j++) {
            const int gn = n0 + tc + j;
            if (gn < N) C[(long)gm * N + gn] = acc[i][j];
        }
    }
}

// ---------------------------------------------------------------------------
// fold_A: AfoldT[b][h*77+t][c] (fp16) = d^-0.5 * sum_e wq[h*160+e][c]*K[b,t][h*160+e]
// ---------------------------------------------------------------------------
__global__ __launch_bounds__(256) void fold_A(
    const float* __restrict__ wq, const float* __restrict__ Kmat,
    __half* __restrict__ outH)
{
    const int b = blockIdx.z, hd = blockIdx.y;
    const int c0 = blockIdx.x * 128;
    __shared__ float Ws[16][128];
    __shared__ float Ks[16][80];

    const int tid  = threadIdx.x;
    const int tcid = tid & 15;
    const int ttid = tid >> 4;
    const float scale = 0.07905694150420949f;

    float acc[8][5];
    #pragma unroll
    for (int i = 0; i < 8; i++)
        #pragma unroll
        for (int j = 0; j < 5; j++) acc[i][j] = 0.f;

    for (int e0 = 0; e0 < DHEAD; e0 += 16) {
        {
            const int cc = (tid & 31) * 4;
            #pragma unroll
            for (int r = 0; r < 2; r++) {
                const int k = (tid >> 5) + r * 8;
                float4 v = *reinterpret_cast<const float4*>(
                    wq + (long)(hd * DHEAD + e0 + k) * DIM + c0 + cc);
                *reinterpret_cast<float4*>(&Ws[k][cc]) = v;
            }
        }
        for (int idx = tid; idx < TOK * 16; idx += 256) {
            const int t = idx >> 4, k = idx & 15;
            Ks[k][t] = Kmat[(long)(b * TOK + t) * DIM + hd * DHEAD + e0 + k];
        }
        for (int idx = tid; idx < 3 * 16; idx += 256)
            Ks[idx & 15][TOK + (idx >> 4)] = 0.f;
        __syncthreads();
        #pragma unroll
        for (int k = 0; k < 16; k++) {
            float w[8], kv[5];
            #pragma unroll
            for (int i = 0; i < 8; i++) w[i] = Ws[k][tcid * 8 + i];
            #pragma unroll
            for (int j = 0; j < 5; j++) kv[j] = Ks[k][ttid * 5 + j];
            #pragma unroll
            for (int i = 0; i < 8; i++)
                #pragma unroll
                for (int j = 0; j < 5; j++)
                    acc[i][j] = fmaf(w[i], kv[j], acc[i][j]);
        }
        __syncthreads();
    }
    #pragma unroll
    for (int i = 0; i < 8; i++) {
        const int c = c0 + tcid * 8 + i;
        #pragma unroll
        for (int j = 0; j < 5; j++) {
            const int t = ttid * 5 + j;
            if (t < TOK) {
                long off = ((long)b * JPAD + hd * TOK + t) * DIM + c;
                outH[off] = __float2half_rn(acc[i][j] * scale);
            }
        }
    }
}

// ---------------------------------------------------------------------------
// fold_B: B2T[b][e2][h*77+t] (fp16) = sum_e V[b,t][h*160+e]*wout[e2][h*160+e]
// ---------------------------------------------------------------------------
__global__ __launch_bounds__(256) void fold_B(
    const float* __restrict__ wout, const float* __restrict__ Vmat,
    __half* __restrict__ outH)
{
    const int b = blockIdx.z, hd = blockIdx.y;
    const int n0 = blockIdx.x * 128;
    __shared__ float Vs[16][80];
    __shared__ float Ws[16][128];

    const int tid  = threadIdx.x;
    const int tcid = tid & 15;
    const int ttid = tid >> 4;

    float acc[5][8];
    #pragma unroll
    for (int j = 0; j < 5; j++)
        #pragma unroll
        for (int i = 0; i < 8; i++) acc[j][i] = 0.f;

    for (int e0 = 0; e0 < DHEAD; e0 += 16) {
        for (int idx = tid; idx < 128 * 16; idx += 256) {
            const int n = idx >> 4, k = idx & 15;
            Ws[k][n] = wout[(long)(n0 + n) * DIM + hd * DHEAD + e0 + k];
        }
        for (int idx = tid; idx < TOK * 16; idx += 256) {
            const int t = idx >> 4, k = idx & 15;
            Vs[k][t] = Vmat[(long)(b * TOK + t) * DIM + hd * DHEAD + e0 + k];
        }
        for (int idx = tid; idx < 3 * 16; idx += 256)
            Vs[idx & 15][TOK + (idx >> 4)] = 0.f;
        __syncthreads();
        #pragma unroll
        for (int k = 0; k < 16; k++) {
            float vv[5], ww[8];
            #pragma unroll
            for (int j = 0; j < 5; j++) vv[j] = Vs[k][ttid * 5 + j];
            #pragma unroll
            for (int i = 0; i < 8; i++) ww[i] = Ws[k][tcid * 8 + i];
            #pragma unroll
            for (int j = 0; j < 5; j++)
                #pragma unroll
                for (int i = 0; i < 8; i++)
                    acc[j][i] = fmaf(vv[j], ww[i], acc[j][i]);
        }
        __syncthreads();
    }
    #pragma unroll
    for (int j = 0; j < 5; j++) {
        const int t = ttid * 5 + j;
        if (t >= TOK) continue;
        #pragma unroll
        for (int i = 0; i < 8; i++) {
            const int n = n0 + tcid * 8 + i;
            long off = ((long)b * DIM + n) * JPAD + hd * TOK + t;
            outH[off] = __float2half_rn(acc[j][i]);
        }
    }
}

// ---------------------------------------------------------------------------
// zero pads (AfoldT rows 616..639; B2T cols 616..639)
// ---------------------------------------------------------------------------
__global__ void zero_pads(__half* A, __half* B2)
{
    const int PAD = JPAD - JDIM;               // 24
    const int n1 = BATCH * PAD * DIM;
    const int n2 = BATCH * DIM * PAD;
    const __half z = __float2half_rn(0.f);
    for (int i = blockIdx.x * blockDim.x + threadIdx.x; i < n1 + n2;
         i += gridDim.x * blockDim.x) {
        if (i < n1) {
            int b = i / (PAD * DIM);
            int rem = i % (PAD * DIM);
            int r = rem / DIM, c = rem % DIM;
            A[((long)b * JPAD + JDIM + r) * DIM + c] = z;
        } else {
            int j = i - n1;
            int b = j / (DIM * PAD);
            int rem = j % (DIM * PAD);
            int e = rem / PAD, t = rem % PAD;
            B2[((long)b * DIM + e) * JPAD + JDIM + t] = z;
        }
    }
}

// ---------------------------------------------------------------------------
// fp32 -> fp16 convert (X)
// ---------------------------------------------------------------------------
__global__ void cvt_h4(const float4* __restrict__ src,
                       __half2* __restrict__ dst, long n4)
{
    for (long i = (long)blockIdx.x * blockDim.x + threadIdx.x; i < n4;
         i += (long)gridDim.x * blockDim.x) {
        float4 v = src[i];
        dst[2 * i]     = __floats2half2_rn(v.x, v.y);
        dst[2 * i + 1] = __floats2half2_rn(v.z, v.w);
    }
}

// ---------------------------------------------------------------------------
// fused softmax(77-group) -> fp16 probs; zeros prob pad cols
// ---------------------------------------------------------------------------
__global__ __launch_bounds__(256) void softmax77h(const float* __restrict__ Smat,
                                                  __half* __restrict__ P)
{
    const int gw   = blockIdx.x * 8 + (threadIdx.x >> 5);
    const int lane = threadIdx.x & 31;
    const int row  = gw >> 3;
    const int h    = gw & 7;
    const long base = (long)row * JPAD + h * TOK;

    const float NEG = -1e30f;
    float x0 = Smat[base + lane];
    float x1 = Smat[base + 32 + lane];
    float x2 = (lane < 13) ? Smat[base + 64 + lane] : NEG;

    float m = fmaxf(x0, fmaxf(x1, x2));
    #pragma unroll
    for (int o = 16; o > 0; o >>= 1)
        m = fmaxf(m, __shfl_xor_sync(0xffffffffu, m, o));

    float e0 = expf(x0 - m);
    float e1 = expf(x1 - m);
    float e2 = (lane < 13) ? expf(x2 - m) : 0.f;
    float s = e0 + e1 + e2;
    #pragma unroll
    for (int o = 16; o > 0; o >>= 1)
        s += __shfl_xor_sync(0xffffffffu, s, o);

    const float inv = 1.f / s;
    P[base + lane]      = __float2half_rn(e0 * inv);
    P[base + 32 + lane] = __float2half_rn(e1 * inv);
    if (lane < 13) P[base + 64 + lane] = __float2half_rn(e2 * inv);
    if (h == 7 && lane < JPAD - JDIM)
        P[(long)row * JPAD + JDIM + lane] = __float2half_rn(0.f);
}

// ---------------------------------------------------------------------------
extern "C" void kernel_launch(void* const* d_in, const int* in_sizes, int n_in,
                              void* d_out, int out_size)
{
    const float* X  = (const float*)d_in[0];
    const float* E  = (const float*)d_in[1];
    const float* wq = (const float*)d_in[2];
    const float* wk = (const float*)d_in[3];
    const float* wv = (const float*)d_in[4];
    const float* wo = (const float*)d_in[5];
    const float* bo = (const float*)d_in[6];
    float* out = (float*)d_out;

    float *pK, *pV, *pS;
    __half *pXf, *pA, *pB2, *pP;
    cudaGetSymbolAddress((void**)&pK,  g_K);
    cudaGetSymbolAddress((void**)&pV,  g_V);
    cudaGetSymbolAddress((void**)&pS,  g_S);
    cudaGetSymbolAddress((void**)&pXf, g_Xf);
    cudaGetSymbolAddress((void**)&pA,  g_A);
    cudaGetSymbolAddress((void**)&pB2, g_B2);
    cudaGetSymbolAddress((void**)&pP,  g_P);

    cudaFuncSetAttribute(mma_gemm, cudaFuncAttributeMaxDynamicSharedMemorySize,
                         MM_SMEM);

    // K/V projections (fp32 SIMT)
    gemm_nt<<<dim3(10, 10, 1), 256>>>(E, wk, pK, BATCH * TOK, DIM, CDIM);
    gemm_nt<<<dim3(10, 10, 1), 256>>>(E, wv, pV, BATCH * TOK, DIM, CDIM);

    // X -> fp16
    cvt_h4<<<8192, 256>>>((const float4*)X, (__half2*)pXf,
                          (long)BATCH * SEQ * DIM / 4);

    // folded operand matrices (fp16, K-major)
    fold_A<<<dim3(10, 8, 16), 256>>>(wq, pK, pA);
    fold_B<<<dim3(10, 8, 16), 256>>>(wo, pV, pB2);
    zero_pads<<<2048, 256>>>(pA, pB2);

    // scores: S[b][s][j] = sum_c X[s][c] * AfoldT[j][c]
    mma_gemm<<<dim3(JPAD / 128, SEQ / 128, BATCH), 256, MM_SMEM>>>(
        pXf, pA, pS, nullptr, DIM, JPAD,
        (long)SEQ * DIM, (long)JPAD * DIM, (long)SEQ * JPAD);

    // fused softmax -> fp16 probs
    softmax77h<<<BATCH * SEQ, 256>>>(pS, pP);

    // output: out[b][s][e] = sum_j P[s][j] * B2T[e][j] + bias[e]
    mma_gemm<<<dim3(DIM / 128, SEQ / 128, BATCH), 256, MM_SMEM>>>(
        pP, pB2, out, bo, JPAD, DIM,
        (long)SEQ * JPAD, (long)DIM * JPAD, (long)SEQ * DIM);
}